// round 8
// baseline (speedup 1.0000x reference)
#include <cuda_runtime.h>
#include <math.h>

typedef unsigned long long u64;

// ---- precomputed-weight layout (u64 units = duplicated f32x2 (w,w));
//      every row starts even & has even length -> 16B-aligned LDS.128 pairs.
#define OFF_A1 0     // 8 rows x 10 (9 + zero pad)
#define OFF_B1 80    // 8 rows x 10
#define OFF_K1 160   // 8 rows x 4
#define OFF_A2 192   // 4 rows x 8
#define OFF_B2 224   // 4 rows x 8
#define OFF_K2 256   // 4 rows x 4
#define OFF_A3 272   // 2 rows x 4
#define OFF_B3 280   // 2 rows x 4
#define OFF_K3 288   // 2 rows x 4
#define OFF_A4 296   // 1 row  x 2
#define OFF_B4 298   // 1 row  x 2
#define OFF_K4 300   // 1 row  x 4
#define W_TOT  304

__device__ __align__(16) u64 g_w[W_TOT];

// ---- f32x2 packed helpers ----
__device__ __forceinline__ u64 pack2(float lo, float hi) {
    u64 r; asm("mov.b64 %0,{%1,%2};" : "=l"(r) : "f"(lo), "f"(hi)); return r;
}
__device__ __forceinline__ void unpack2(u64 v, float& lo, float& hi) {
    asm("mov.b64 {%0,%1},%2;" : "=f"(lo), "=f"(hi) : "l"(v));
}
__device__ __forceinline__ u64 ffma2(u64 a, u64 b, u64 c) {
    u64 d; asm("fma.rn.f32x2 %0,%1,%2,%3;" : "=l"(d) : "l"(a), "l"(b), "l"(c)); return d;
}
__device__ __forceinline__ u64 fmul2(u64 a, u64 b) {
    u64 d; asm("mul.rn.f32x2 %0,%1,%2;" : "=l"(d) : "l"(a), "l"(b)); return d;
}
// 16B shared load of a u64 pair
__device__ __forceinline__ void lds2(const u64* p, u64& w0, u64& w1) {
    ulonglong2 v = *(const ulonglong2*)p; w0 = v.x; w1 = v.y;
}

// ---- prep: softmax the tiny weight tensors once, store duplicated ----
__device__ void softmax_dup(const float* src, int len, int off, int pad) {
    float m = src[0];
    for (int i = 1; i < len; i++) m = fmaxf(m, src[i]);
    float s = 0.f;
    for (int i = 0; i < len; i++) s += expf(src[i] - m);
    float inv = 1.f / s;
    for (int i = 0; i < len; i++) {
        float v = expf(src[i] - m) * inv;
        g_w[off + i] = pack2(v, v);
    }
    for (int i = len; i < len + pad; i++) g_w[off + i] = 0ull;
}

// Collapse 16 probabilistic gates to out = c0 + c1*p + c2*q + c3*p*q
__device__ void gate_dup(const float* g, int off) {
    float m = g[0];
    for (int i = 1; i < 16; i++) m = fmaxf(m, g[i]);
    float w[16]; float s = 0.f;
    for (int i = 0; i < 16; i++) { w[i] = expf(g[i] - m); s += w[i]; }
    float inv = 1.f / s;
    for (int i = 0; i < 16; i++) w[i] *= inv;
    float c0 = w[8] + w[9] + w[10] + w[11] + w[12] + w[13] + w[14] + w[15];
    float c1 = w[2] + w[3] + w[6] + w[7] - w[8] - w[9] - w[12] - w[13];
    float c2 = w[4] + w[5] + w[6] + w[7] - w[8] - w[9] - w[10] - w[11];
    float c3 = w[1] - w[2] - w[4] - 2.f * w[6] - w[7] + w[8] + 2.f * w[9]
             + w[11] + w[13] - w[14];
    g_w[off + 0] = pack2(c0, c0);
    g_w[off + 1] = pack2(c1, c1);
    g_w[off + 2] = pack2(c2, c2);
    g_w[off + 3] = pack2(c3, c3);
}

// 64 threads; one softmax or one gate-collapse per thread (45 active).
__global__ void prep_kernel(
    const float* sa1, const float* sb1, const float* g1,
    const float* sa2, const float* sb2, const float* g2,
    const float* sa3, const float* sb3, const float* g3,
    const float* sa4, const float* sb4, const float* g4)
{
    int t = threadIdx.x;
    int kind = t >> 4;      // 0 = sel_a, 1 = sel_b, 2 = gates
    int r = t & 15;         // global row index 0..14
    if (kind > 2 || r > 14) return;

    int L, row;
    if (r < 8)       { L = 0; row = r; }
    else if (r < 12) { L = 1; row = r - 8; }
    else if (r < 14) { L = 2; row = r - 12; }
    else             { L = 3; row = 0; }

    const int NI[4]    = {9, 8, 4, 2};
    const int STR[4]   = {10, 8, 4, 2};   // padded row stride in u64
    const int PAD[4]   = {1, 0, 0, 0};
    const int offA[4] = {OFF_A1, OFF_A2, OFF_A3, OFF_A4};
    const int offB[4] = {OFF_B1, OFF_B2, OFF_B3, OFF_B4};
    const int offK[4] = {OFF_K1, OFF_K2, OFF_K3, OFF_K4};
    const float* SA[4] = {sa1, sa2, sa3, sa4};
    const float* SB[4] = {sb1, sb2, sb3, sb4};
    const float* GG[4] = {g1, g2, g3, g4};

    int ni = NI[L], st = STR[L], pd = PAD[L];
    if (kind == 0)      softmax_dup(SA[L] + row * ni, ni, offA[L] + row * st, pd);
    else if (kind == 1) softmax_dup(SB[L] + row * ni, ni, offB[L] + row * st, pd);
    else                gate_dup(GG[L] + row * 16, offK[L] + row * 4);
}

// ---- one layer, 4 cells as 2 cell-pairs (lanes = 2 cells). Weight loads
//      (LDS.128 dup pairs) shared across both cell-pairs. No inter-layer
//      repacking: outputs are cell-pair u64, same as inputs. AS = row stride.
template <int NI, int NO, int AS>
__device__ __forceinline__ void layer(
    const u64* __restrict__ sa, const u64* __restrict__ sb,
    const u64* __restrict__ sk,
    const u64* inU, const u64* inV, u64* outU, u64* outV)
{
#pragma unroll
    for (int n = 0; n < NO; n++) {
        const u64* a = sa + n * AS;
        const u64* b = sb + n * AS;
        u64 a0, a1, b0, b1;
        lds2(a, a0, a1);
        lds2(b, b0, b1);
        u64 pU = fmul2(inU[0], a0), qU = fmul2(inU[0], b0);
        u64 pV = fmul2(inV[0], a0), qV = fmul2(inV[0], b0);
        if (NI > 1) {
            pU = ffma2(inU[1], a1, pU); qU = ffma2(inU[1], b1, qU);
            pV = ffma2(inV[1], a1, pV); qV = ffma2(inV[1], b1, qV);
        }
#pragma unroll
        for (int i = 2; i < NI; i += 2) {
            lds2(a + i, a0, a1);
            lds2(b + i, b0, b1);
            pU = ffma2(inU[i], a0, pU); qU = ffma2(inU[i], b0, qU);
            pV = ffma2(inV[i], a0, pV); qV = ffma2(inV[i], b0, qV);
            if (i + 1 < NI) {
                pU = ffma2(inU[i + 1], a1, pU); qU = ffma2(inU[i + 1], b1, qU);
                pV = ffma2(inV[i + 1], a1, pV); qV = ffma2(inV[i + 1], b1, qV);
            }
        }
        u64 k0, k1, k2, k3;
        lds2(sk + n * 4, k0, k1);
        lds2(sk + n * 4 + 2, k2, k3);
        // h = c0 + c1 p + c2 q + c3 pq = p*(c1 + c3 q) + (c0 + c2 q)
        u64 t1U = ffma2(k3, qU, k1);
        u64 t0U = ffma2(k2, qU, k0);
        outU[n] = ffma2(pU, t1U, t0U);
        u64 t1V = ffma2(k3, qV, k1);
        u64 t0V = ffma2(k2, qV, k0);
        outV[n] = ffma2(pV, t1V, t0V);
    }
}

#define CELLS_PER_BLOCK 1024
#define SXF (CELLS_PER_BLOCK * 9)   // 9216 floats = 36 KB

// 256 threads/block, 1024 cells/block, 4 consecutive cells per thread.
__global__ void __launch_bounds__(256, 3) logicnet_main(
    const float* __restrict__ x, float* __restrict__ out, int B)
{
    __shared__ __align__(16) u64 sw[W_TOT];   // 2432 B
    __shared__ float sx[SXF];                 // 36 KB staging

    int t = threadIdx.x;

    // Broadcast precomputed weights to SMEM (152 x 16B).
#pragma unroll
    for (int i = t; i < W_TOT / 2; i += 256)
        ((ulonglong2*)sw)[i] = ((const ulonglong2*)g_w)[i];

    // Coalesced float4 staging: 2304 float4 per block = 9 per thread exactly.
    long gbaseF = (long)blockIdx.x * SXF;
    long totalF = (long)B * 9;
    const float4* gx4 = (const float4*)(x + gbaseF);
    float4* sx4 = (float4*)sx;
    if (gbaseF + SXF <= totalF) {
#pragma unroll
        for (int k = 0; k < 9; k++) {
            int li = t + k * 256;
            sx4[li] = gx4[li];
        }
    } else {
        for (int li = t; li < SXF / 4; li += 256) {
            long gi = gbaseF + (long)li * 4;
            float4 v;
            v.x = (gi + 0 < totalF) ? x[gi + 0] : 0.f;
            v.y = (gi + 1 < totalF) ? x[gi + 1] : 0.f;
            v.z = (gi + 2 < totalF) ? x[gi + 2] : 0.f;
            v.w = (gi + 3 < totalF) ? x[gi + 3] : 0.f;
            sx4[li] = v;
        }
    }
    __syncthreads();

    // This thread's 4 consecutive cells = 36 contiguous floats.
    // 9 LDS.128, word stride 36 ≡ 4 (mod 32): conflict-free.
    float v[36];
    const float4* cx4 = (const float4*)(sx + t * 36);
#pragma unroll
    for (int k = 0; k < 9; k++) {
        float4 q = cx4[k];
        v[4 * k + 0] = q.x; v[4 * k + 1] = q.y;
        v[4 * k + 2] = q.z; v[4 * k + 3] = q.w;
    }

    // Cell-pair lanes: U = (cell0, cell1), V = (cell2, cell3).
    u64 xU[9], xV[9];
#pragma unroll
    for (int i = 0; i < 9; i++) {
        xU[i] = pack2(v[i],      v[9 + i]);
        xV[i] = pack2(v[18 + i], v[27 + i]);
    }

    u64 h1U[8], h1V[8];
    layer<9, 8, 10>(sw + OFF_A1, sw + OFF_B1, sw + OFF_K1, xU, xV, h1U, h1V);
    u64 h2U[4], h2V[4];
    layer<8, 4, 8>(sw + OFF_A2, sw + OFF_B2, sw + OFF_K2, h1U, h1V, h2U, h2V);
    u64 h3U[2], h3V[2];
    layer<4, 2, 4>(sw + OFF_A3, sw + OFF_B3, sw + OFF_K3, h2U, h2V, h3U, h3V);
    u64 h4U[1], h4V[1];
    layer<2, 1, 2>(sw + OFF_A4, sw + OFF_B4, sw + OFF_K4, h3U, h3V, h4U, h4V);

    float r0, r1, r2, r3;
    unpack2(h4U[0], r0, r1);
    unpack2(h4V[0], r2, r3);

    long cbase = (long)blockIdx.x * CELLS_PER_BLOCK + (long)t * 4;
    if (cbase + 3 < B) {
        *(float4*)(out + cbase) = make_float4(r0, r1, r2, r3);
    } else {
        if (cbase + 0 < B) out[cbase + 0] = r0;
        if (cbase + 1 < B) out[cbase + 1] = r1;
        if (cbase + 2 < B) out[cbase + 2] = r2;
        if (cbase + 3 < B) out[cbase + 3] = r3;
    }
}

extern "C" void kernel_launch(void* const* d_in, const int* in_sizes, int n_in,
                              void* d_out, int out_size)
{
    const float* x = (const float*)d_in[0];
    prep_kernel<<<1, 64>>>(
        (const float*)d_in[1], (const float*)d_in[2], (const float*)d_in[3],
        (const float*)d_in[4], (const float*)d_in[5], (const float*)d_in[6],
        (const float*)d_in[7], (const float*)d_in[8], (const float*)d_in[9],
        (const float*)d_in[10], (const float*)d_in[11], (const float*)d_in[12]);

    int B = in_sizes[0] / 9;
    int blocks = (B + CELLS_PER_BLOCK - 1) / CELLS_PER_BLOCK;
    logicnet_main<<<blocks, 256>>>(x, (float*)d_out, B);
}

// round 9
// speedup vs baseline: 1.2536x; 1.2536x over previous
#include <cuda_runtime.h>
#include <math.h>

typedef unsigned long long u64;

// ---- weight SMEM layout (floats).
//      sel weights interleaved per node row: (a_0,b_0,a_1,b_1,...)
//      gate coefs per node: (c0,c1,c2,c3), 16B-aligned.
#define OFF_AB1 0     // 8 nodes x 9 pairs = 144 floats
#define OFF_K1  144   // 8 x 4 = 32
#define OFF_AB2 176   // 4 x 8 pairs = 64
#define OFF_K2  240   // 4 x 4 = 16
#define OFF_AB3 256   // 2 x 4 pairs = 16
#define OFF_K3  272   // 2 x 4 = 8
#define OFF_AB4 280   // 1 x 2 pairs = 4
#define OFF_K4  284   // 1 x 4 = 4
#define WF_TOT  288   // 1152 B

// ---- f32x2 packed helpers ----
__device__ __forceinline__ u64 pack2(float lo, float hi) {
    u64 r; asm("mov.b64 %0,{%1,%2};" : "=l"(r) : "f"(lo), "f"(hi)); return r;
}
__device__ __forceinline__ void unpack2(u64 v, float& lo, float& hi) {
    asm("mov.b64 {%0,%1},%2;" : "=f"(lo), "=f"(hi) : "l"(v));
}
__device__ __forceinline__ u64 ffma2(u64 a, u64 b, u64 c) {
    u64 d; asm("fma.rn.f32x2 %0,%1,%2,%3;" : "=l"(d) : "l"(a), "l"(b), "l"(c)); return d;
}
__device__ __forceinline__ u64 fmul2(u64 a, u64 b) {
    u64 d; asm("mul.rn.f32x2 %0,%1,%2;" : "=l"(d) : "l"(a), "l"(b)); return d;
}

// ---- in-block prep: softmaxes into interleaved (a,b) slots; gates collapsed
__device__ void softmax_slot_s(float* swf, const float* src, int len, int off, int lane) {
    float m = src[0];
    for (int i = 1; i < len; i++) m = fmaxf(m, src[i]);
    float s = 0.f;
    for (int i = 0; i < len; i++) s += expf(src[i] - m);
    float inv = 1.f / s;
    for (int i = 0; i < len; i++)
        swf[off + 2 * i + lane] = expf(src[i] - m) * inv;
}

// Collapse 16 probabilistic gates to out = c0 + c1*p + c2*q + c3*p*q
__device__ void gate_coefs_s(float* swf, const float* g, int off) {
    float m = g[0];
    for (int i = 1; i < 16; i++) m = fmaxf(m, g[i]);
    float w[16]; float s = 0.f;
    for (int i = 0; i < 16; i++) { w[i] = expf(g[i] - m); s += w[i]; }
    float inv = 1.f / s;
    for (int i = 0; i < 16; i++) w[i] *= inv;
    float c0 = w[8] + w[9] + w[10] + w[11] + w[12] + w[13] + w[14] + w[15];
    float c1 = w[2] + w[3] + w[6] + w[7] - w[8] - w[9] - w[12] - w[13];
    float c2 = w[4] + w[5] + w[6] + w[7] - w[8] - w[9] - w[10] - w[11];
    float c3 = w[1] - w[2] - w[4] - 2.f * w[6] - w[7] + w[8] + 2.f * w[9]
             + w[11] + w[13] - w[14];
    swf[off + 0] = c0; swf[off + 1] = c1;
    swf[off + 2] = c2; swf[off + 3] = c3;
}

// ---- one layer, 3 cells/thread. Lanes = (p,q); weights = (a_i,b_i) pairs,
//      loaded once per node (LDS.64) and shared across the 3 cells.
template <int NI, int NO>
__device__ __forceinline__ void layer3c(
    const float* __restrict__ sw, int offAB, int offK,
    const u64* in0, const u64* in1, const u64* in2,
    float* o0, float* o1, float* o2)
{
    const u64* ab_base = (const u64*)(sw + offAB);
    const float4* kv = (const float4*)(sw + offK);
#pragma unroll
    for (int n = 0; n < NO; n++) {
        const u64* ab = ab_base + n * NI;
        u64 w = ab[0];
        u64 a0 = fmul2(in0[0], w);
        u64 a1 = fmul2(in1[0], w);
        u64 a2 = fmul2(in2[0], w);
#pragma unroll
        for (int i = 1; i < NI; i++) {
            w = ab[i];
            a0 = ffma2(in0[i], w, a0);
            a1 = ffma2(in1[i], w, a1);
            a2 = ffma2(in2[i], w, a2);
        }
        float4 k = kv[n];
        float p, q;
        // h = c0 + c1 p + c2 q + c3 pq = p*(c1 + c3 q) + (c0 + c2 q)
        unpack2(a0, p, q);
        o0[n] = fmaf(p, fmaf(k.w, q, k.y), fmaf(k.z, q, k.x));
        unpack2(a1, p, q);
        o1[n] = fmaf(p, fmaf(k.w, q, k.y), fmaf(k.z, q, k.x));
        unpack2(a2, p, q);
        o2[n] = fmaf(p, fmaf(k.w, q, k.y), fmaf(k.z, q, k.x));
    }
}

#define CPB 768                 // cells per block (3 per thread)
#define SXF (CPB * 9)           // 6912 floats = 27 KB
#define NF4 (SXF / 4)           // 1728 float4

// 256 threads/block, 768 cells/block, 3 consecutive cells per thread.
__global__ void __launch_bounds__(256, 3) logicnet_main(
    const float* __restrict__ x, float* __restrict__ out, int B,
    const float* __restrict__ sa1, const float* __restrict__ sb1, const float* __restrict__ g1,
    const float* __restrict__ sa2, const float* __restrict__ sb2, const float* __restrict__ g2,
    const float* __restrict__ sa3, const float* __restrict__ sb3, const float* __restrict__ g3,
    const float* __restrict__ sa4, const float* __restrict__ sb4, const float* __restrict__ g4)
{
    __shared__ __align__(16) float swf[WF_TOT];   // 1152 B weights
    __shared__ float sx[SXF];                     // 27 KB x staging

    int t = threadIdx.x;

    // In-block prep: 45 threads compute all softmaxes/gate-collapses directly
    // into SMEM (redundantly per block; inputs are tiny and L2-resident).
    if (t < 45) {
        int kind = t / 15;      // 0 = sel_a, 1 = sel_b, 2 = gates
        int r = t % 15;
        int L, row;
        if (r < 8)       { L = 0; row = r; }
        else if (r < 12) { L = 1; row = r - 8; }
        else if (r < 14) { L = 2; row = r - 12; }
        else             { L = 3; row = 0; }

        const int NI[4]    = {9, 8, 4, 2};
        const int offAB[4] = {OFF_AB1, OFF_AB2, OFF_AB3, OFF_AB4};
        const int offK[4]  = {OFF_K1, OFF_K2, OFF_K3, OFF_K4};
        const float* SA[4] = {sa1, sa2, sa3, sa4};
        const float* SB[4] = {sb1, sb2, sb3, sb4};
        const float* GG[4] = {g1, g2, g3, g4};

        int ni = NI[L];
        if (kind == 0)      softmax_slot_s(swf, SA[L] + row * ni, ni, offAB[L] + row * 2 * ni, 0);
        else if (kind == 1) softmax_slot_s(swf, SB[L] + row * ni, ni, offAB[L] + row * 2 * ni, 1);
        else                gate_coefs_s(swf, GG[L] + row * 16, offK[L] + row * 4);
    }

    // Coalesced float4 staging of x: 1728 float4 per block.
    long gbaseF = (long)blockIdx.x * SXF;
    long totalF = (long)B * 9;
    const float4* gx4 = (const float4*)(x + gbaseF);
    float4* sx4 = (float4*)sx;
    if (gbaseF + SXF <= totalF) {
#pragma unroll
        for (int k = 0; k < 7; k++) {
            int li = t + k * 256;
            if (li < NF4) sx4[li] = gx4[li];
        }
    } else {
        for (int li = t; li < NF4; li += 256) {
            long gi = gbaseF + (long)li * 4;
            float4 v;
            v.x = (gi + 0 < totalF) ? x[gi + 0] : 0.f;
            v.y = (gi + 1 < totalF) ? x[gi + 1] : 0.f;
            v.z = (gi + 2 < totalF) ? x[gi + 2] : 0.f;
            v.w = (gi + 3 < totalF) ? x[gi + 3] : 0.f;
            sx4[li] = v;
        }
    }
    __syncthreads();

    // This thread's 3 consecutive cells = 27 contiguous floats.
    // Scalar LDS, word stride 27 (odd) → conflict-free.
    float v[27];
    const float* cx = sx + t * 27;
#pragma unroll
    for (int i = 0; i < 27; i++) v[i] = cx[i];

    // Duplicate inputs into f32x2 lanes (lanes carry the (p,q) operand pair).
    u64 i0[9], i1[9], i2[9];
#pragma unroll
    for (int i = 0; i < 9; i++) {
        i0[i] = pack2(v[i],      v[i]);
        i1[i] = pack2(v[9 + i],  v[9 + i]);
        i2[i] = pack2(v[18 + i], v[18 + i]);
    }

    float f0[8], f1[8], f2[8];
    layer3c<9, 8>(swf, OFF_AB1, OFF_K1, i0, i1, i2, f0, f1, f2);

    u64 j0[8], j1[8], j2[8];
#pragma unroll
    for (int i = 0; i < 8; i++) {
        j0[i] = pack2(f0[i], f0[i]);
        j1[i] = pack2(f1[i], f1[i]);
        j2[i] = pack2(f2[i], f2[i]);
    }
    float e0[4], e1[4], e2[4];
    layer3c<8, 4>(swf, OFF_AB2, OFF_K2, j0, j1, j2, e0, e1, e2);

    u64 k0[4], k1[4], k2[4];
#pragma unroll
    for (int i = 0; i < 4; i++) {
        k0[i] = pack2(e0[i], e0[i]);
        k1[i] = pack2(e1[i], e1[i]);
        k2[i] = pack2(e2[i], e2[i]);
    }
    float d0[2], d1[2], d2[2];
    layer3c<4, 2>(swf, OFF_AB3, OFF_K3, k0, k1, k2, d0, d1, d2);

    u64 m0[2], m1[2], m2[2];
#pragma unroll
    for (int i = 0; i < 2; i++) {
        m0[i] = pack2(d0[i], d0[i]);
        m1[i] = pack2(d1[i], d1[i]);
        m2[i] = pack2(d2[i], d2[i]);
    }
    float r0[1], r1[1], r2[1];
    layer3c<2, 1>(swf, OFF_AB4, OFF_K4, m0, m1, m2, r0, r1, r2);

    long cbase = (long)blockIdx.x * CPB + (long)t * 3;
    if (cbase + 2 < B) {
        out[cbase + 0] = r0[0];
        out[cbase + 1] = r1[0];
        out[cbase + 2] = r2[0];
    } else {
        if (cbase + 0 < B) out[cbase + 0] = r0[0];
        if (cbase + 1 < B) out[cbase + 1] = r1[0];
        if (cbase + 2 < B) out[cbase + 2] = r2[0];
    }
}

extern "C" void kernel_launch(void* const* d_in, const int* in_sizes, int n_in,
                              void* d_out, int out_size)
{
    const float* x = (const float*)d_in[0];
    int B = in_sizes[0] / 9;
    int blocks = (B + CPB - 1) / CPB;
    logicnet_main<<<blocks, 256>>>(
        x, (float*)d_out, B,
        (const float*)d_in[1], (const float*)d_in[2], (const float*)d_in[3],
        (const float*)d_in[4], (const float*)d_in[5], (const float*)d_in[6],
        (const float*)d_in[7], (const float*)d_in[8], (const float*)d_in[9],
        (const float*)d_in[10], (const float*)d_in[11], (const float*)d_in[12]);
}